// round 14
// baseline (speedup 1.0000x reference)
#include <cuda_runtime.h>
#include <cuda_bf16.h>
#include <mma.h>

using namespace nvcuda;

// Problem dims (fixed by the reference)
#define Gn   32
#define NN   4000
#define EE   32000
#define FD0  64
#define HD   128
#define BNR  16000
#define STEPS 8

typedef unsigned long long u64;

__device__ __forceinline__ void split_bf16(float v, __nv_bfloat16& hi, __nv_bfloat16& lo) {
    hi = __float2bfloat16(v);
    lo = __float2bfloat16(v - __bfloat162float(hi));
}
__device__ __forceinline__ float sigmoidf_(float x) { return 1.f / (1.f + __expf(-x)); }

// ---------------- scratch (device globals) --------------------------------------
__device__ float d_deg_out[Gn * NN];
__device__ float d_deg_in [Gn * NN];
__device__ int   d_cnt_f[Gn * NN];
__device__ int   d_cnt_b[Gn * NN];
__device__ int   d_off_f[Gn * NN];
__device__ int   d_off_b[Gn * NN];
__device__ int   d_cur_f[Gn * NN];
__device__ int   d_cur_b[Gn * NN];
__device__ int   d_csr_if[Gn * EE];
__device__ float d_csr_wf[Gn * EE];
__device__ int   d_csr_ib[Gn * EE];
__device__ float d_csr_wb[Gn * EE];
// aggregation outputs, bf16 hi/lo
__device__ __nv_bfloat16 d_aggfh[(size_t)Gn * NN * HD];
__device__ __nv_bfloat16 d_aggfl[(size_t)Gn * NN * HD];
__device__ __nv_bfloat16 d_aggbh[(size_t)Gn * NN * HD];
__device__ __nv_bfloat16 d_aggbl[(size_t)Gn * NN * HD];
__device__ float d_h0    [(size_t)Gn * NN * HD];
__device__ float d_gx    [(size_t)BNR * STEPS * 4 * HD];
// bf16x3 weight/input images
__device__ __nv_bfloat16 d_h1hi[(size_t)Gn * NN * HD];
__device__ __nv_bfloat16 d_h1lo[(size_t)Gn * NN * HD];
__device__ __nv_bfloat16 d_wihhi[512 * 128];
__device__ __nv_bfloat16 d_wihlo[512 * 128];
__device__ __nv_bfloat16 d_whhhi[512 * 128];   // Whh [n=512][k=128] hi/lo
__device__ __nv_bfloat16 d_whhlo[512 * 128];
__device__ __nv_bfloat16 d_wphi [FD0 * HD];    // Wp [n=64][k=128] hi/lo
__device__ __nv_bfloat16 d_wplo [FD0 * HD];
__device__ float d_bsum[512];                  // bih + bhh
__device__ __nv_bfloat16 d_w0sh[HD * FD0], d_w0sl[HD * FD0];
__device__ __nv_bfloat16 d_w0dh[HD * FD0], d_w0dl[HD * FD0];
__device__ __nv_bfloat16 d_w1sh[HD * HD],  d_w1sl[HD * HD];
__device__ __nv_bfloat16 d_w1dh[HD * HD],  d_w1dl[HD * HD];
__device__ float d_b0v[HD];
__device__ float d_b1v[HD];

// ---------------- CSR build ------------------------------------------------------
__global__ void zero_kernel() {
    int i = blockIdx.x * blockDim.x + threadIdx.x;
    if (i < Gn * NN) {
        d_deg_out[i] = 0.f; d_deg_in[i] = 0.f;
        d_cnt_f[i] = 0;     d_cnt_b[i] = 0;
    }
}

__global__ void degcnt_kernel(const int* __restrict__ ei, const float* __restrict__ ew) {
    int i = blockIdx.x * blockDim.x + threadIdx.x;
    if (i >= Gn * EE) return;
    int g = i / EE, e = i - g * EE;
    const int* eig = ei + (size_t)g * 2 * EE;
    int src = eig[e], dst = eig[EE + e];
    float w = ew[i];
    atomicAdd(&d_deg_out[g * NN + src], w);
    atomicAdd(&d_deg_in [g * NN + dst], w);
    atomicAdd(&d_cnt_f[g * NN + dst], 1);
    atomicAdd(&d_cnt_b[g * NN + src], 1);
}

__global__ void inv_kernel() {
    int i = blockIdx.x * blockDim.x + threadIdx.x;
    if (i >= Gn * NN) return;
    float v = d_deg_out[i];
    d_deg_out[i] = (v > 0.f) ? rsqrtf(fmaxf(v, 1e-12f)) : 0.f;
    v = d_deg_in[i];
    d_deg_in[i]  = (v > 0.f) ? rsqrtf(fmaxf(v, 1e-12f)) : 0.f;
}

__global__ void __launch_bounds__(1024) scan_kernel() {
    int g   = blockIdx.x;
    int dir = blockIdx.y;
    const int* cnt = dir ? d_cnt_b : d_cnt_f;
    int* off = dir ? d_off_b : d_off_f;
    int* cur = dir ? d_cur_b : d_cur_f;
    int tid = threadIdx.x;
    int base = g * NN;
    int v[4], tot = 0;
#pragma unroll
    for (int k = 0; k < 4; k++) {
        int i = tid * 4 + k;
        v[k] = (i < NN) ? cnt[base + i] : 0;
        tot += v[k];
    }
    __shared__ int s[1024];
    s[tid] = tot;
    __syncthreads();
    for (int d = 1; d < 1024; d <<= 1) {
        int t = (tid >= d) ? s[tid - d] : 0;
        __syncthreads();
        s[tid] += t;
        __syncthreads();
    }
    int ex = s[tid] - tot;
#pragma unroll
    for (int k = 0; k < 4; k++) {
        int i = tid * 4 + k;
        if (i < NN) { off[base + i] = ex; cur[base + i] = ex; ex += v[k]; }
    }
}

__global__ void scatter_kernel(const int* __restrict__ ei, const float* __restrict__ ew) {
    int i = blockIdx.x * blockDim.x + threadIdx.x;
    if (i >= Gn * EE) return;
    int g = i / EE, e = i - g * EE;
    const int* eig = ei + (size_t)g * 2 * EE;
    int src = eig[e], dst = eig[EE + e];
    float w = ew[i] * d_deg_out[g * NN + src] * d_deg_in[g * NN + dst];
    int pf = atomicAdd(&d_cur_f[g * NN + dst], 1);
    d_csr_if[g * EE + pf] = src;
    d_csr_wf[g * EE + pf] = w;
    int pb = atomicAdd(&d_cur_b[g * NN + src], 1);
    d_csr_ib[g * EE + pb] = dst;
    d_csr_wb[g * EE + pb] = w;
}

// ---------------- gather aggregation (round-13, unchanged) -----------------------
template<int FD>
__global__ void __launch_bounds__(256) gather_kernel(const float* __restrict__ x) {
    int gw = (blockIdx.x * 256 + threadIdx.x) >> 5;
    int lane = threadIdx.x & 31;
    if (gw >= Gn * NN * 2) return;
    int dir = gw & 1;
    int gn  = gw >> 1;
    int g   = gn / NN;
    const int*   off = dir ? d_off_b : d_off_f;
    const int*   cnt = dir ? d_cnt_b : d_cnt_f;
    const int*   nb  = dir ? d_csr_ib : d_csr_if;
    const float* wv  = dir ? d_csr_wb : d_csr_wf;
    __nv_bfloat16* oh = dir ? d_aggbh : d_aggfh;
    __nv_bfloat16* ol = dir ? d_aggbl : d_aggfl;
    int o = off[gn], c = cnt[gn];
    const float* xg = x + (size_t)g * NN * FD;
    const int ebase = g * EE + o;

    if (FD == 128) {
        float4 acc = make_float4(0.f, 0.f, 0.f, 0.f);
        int j = 0;
        for (; j + 4 <= c; j += 4) {
            int   s0 = nb[ebase + j],     s1 = nb[ebase + j + 1];
            int   s2 = nb[ebase + j + 2], s3 = nb[ebase + j + 3];
            float w0 = wv[ebase + j],     w1 = wv[ebase + j + 1];
            float w2 = wv[ebase + j + 2], w3 = wv[ebase + j + 3];
            float4 x0 = *(const float4*)(xg + (size_t)s0 * FD + lane * 4);
            float4 x1 = *(const float4*)(xg + (size_t)s1 * FD + lane * 4);
            float4 x2 = *(const float4*)(xg + (size_t)s2 * FD + lane * 4);
            float4 x3 = *(const float4*)(xg + (size_t)s3 * FD + lane * 4);
            acc.x += w0 * x0.x; acc.y += w0 * x0.y; acc.z += w0 * x0.z; acc.w += w0 * x0.w;
            acc.x += w1 * x1.x; acc.y += w1 * x1.y; acc.z += w1 * x1.z; acc.w += w1 * x1.w;
            acc.x += w2 * x2.x; acc.y += w2 * x2.y; acc.z += w2 * x2.z; acc.w += w2 * x2.w;
            acc.x += w3 * x3.x; acc.y += w3 * x3.y; acc.z += w3 * x3.z; acc.w += w3 * x3.w;
        }
        for (; j < c; j++) {
            int   s = nb[ebase + j];
            float w = wv[ebase + j];
            float4 xv = *(const float4*)(xg + (size_t)s * FD + lane * 4);
            acc.x += w * xv.x; acc.y += w * xv.y;
            acc.z += w * xv.z; acc.w += w * xv.w;
        }
        __nv_bfloat16 hx, lx, hy, ly, hz, lz, hw, lw;
        split_bf16(acc.x, hx, lx); split_bf16(acc.y, hy, ly);
        split_bf16(acc.z, hz, lz); split_bf16(acc.w, hw, lw);
        size_t p = (size_t)gn * FD + lane * 4;
        *(__nv_bfloat162*)(oh + p)     = __nv_bfloat162(hx, hy);
        *(__nv_bfloat162*)(oh + p + 2) = __nv_bfloat162(hz, hw);
        *(__nv_bfloat162*)(ol + p)     = __nv_bfloat162(lx, ly);
        *(__nv_bfloat162*)(ol + p + 2) = __nv_bfloat162(lz, lw);
    } else {
        float2 acc = make_float2(0.f, 0.f);
        int j = 0;
        for (; j + 4 <= c; j += 4) {
            int   s0 = nb[ebase + j],     s1 = nb[ebase + j + 1];
            int   s2 = nb[ebase + j + 2], s3 = nb[ebase + j + 3];
            float w0 = wv[ebase + j],     w1 = wv[ebase + j + 1];
            float w2 = wv[ebase + j + 2], w3 = wv[ebase + j + 3];
            float2 x0 = *(const float2*)(xg + (size_t)s0 * FD + lane * 2);
            float2 x1 = *(const float2*)(xg + (size_t)s1 * FD + lane * 2);
            float2 x2 = *(const float2*)(xg + (size_t)s2 * FD + lane * 2);
            float2 x3 = *(const float2*)(xg + (size_t)s3 * FD + lane * 2);
            acc.x += w0 * x0.x; acc.y += w0 * x0.y;
            acc.x += w1 * x1.x; acc.y += w1 * x1.y;
            acc.x += w2 * x2.x; acc.y += w2 * x2.y;
            acc.x += w3 * x3.x; acc.y += w3 * x3.y;
        }
        for (; j < c; j++) {
            int   s = nb[ebase + j];
            float w = wv[ebase + j];
            float2 xv = *(const float2*)(xg + (size_t)s * FD + lane * 2);
            acc.x += w * xv.x; acc.y += w * xv.y;
        }
        __nv_bfloat16 hx, lx, hy, ly;
        split_bf16(acc.x, hx, lx); split_bf16(acc.y, hy, ly);
        size_t p = (size_t)gn * FD + lane * 2;
        *(__nv_bfloat162*)(oh + p) = __nv_bfloat162(hx, hy);
        *(__nv_bfloat162*)(ol + p) = __nv_bfloat162(lx, ly);
    }
}

// ---------------- GCN dual GEMM via WMMA bf16x3 (round-13, unchanged) ------------
template<int KD, bool SPLIT_OUT>
__global__ void __launch_bounds__(256)
gcn_wmma_kernel(const __nv_bfloat16* __restrict__ A0h, const __nv_bfloat16* __restrict__ A0l,
                const __nv_bfloat16* __restrict__ A1h, const __nv_bfloat16* __restrict__ A1l,
                const __nv_bfloat16* __restrict__ W0h, const __nv_bfloat16* __restrict__ W0l,
                const __nv_bfloat16* __restrict__ W1h, const __nv_bfloat16* __restrict__ W1l,
                const float* __restrict__ bias, float* __restrict__ C,
                __nv_bfloat16* __restrict__ Chi, __nv_bfloat16* __restrict__ Clo)
{
    constexpr int LD = KD + 8;
    extern __shared__ char smem[];
    __nv_bfloat16* AH = (__nv_bfloat16*)smem;
    __nv_bfloat16* AL = AH + 128 * LD;
    __nv_bfloat16* BH = AL + 128 * LD;
    __nv_bfloat16* BL = BH + 128 * LD;
    float*         BI = (float*)(BL + 128 * LD);

    const int tid = threadIdx.x;
    const int wid = tid >> 5;
    const int m0  = blockIdx.x * 128;
    const int m_off = (wid >> 1) * 32;
    const int n_off = (wid & 1) * 64;
    constexpr int CPR = KD / 8;

#pragma unroll
    for (int t = 0; t < 8; t++) {
        int i = tid + t * 256;
        BI[i] = bias[i & 127];
    }

    wmma::fragment<wmma::accumulator, 16, 16, 16, float> acc[2][4];

    for (int dir = 0; dir < 2; dir++) {
        const __nv_bfloat16* Ah = dir ? A1h : A0h;
        const __nv_bfloat16* Al = dir ? A1l : A0l;
        const __nv_bfloat16* Wh = dir ? W1h : W0h;
        const __nv_bfloat16* Wl = dir ? W1l : W0l;
        if (dir) __syncthreads();
#pragma unroll
        for (int t = 0; t < KD / 16; t++) {
            int ch = tid + t * 256;
            int r  = ch / CPR;
            int c8 = ch % CPR;
            *(uint4*)(AH + r * LD + c8 * 8) = *(const uint4*)(Ah + (size_t)(m0 + r) * KD + c8 * 8);
            *(uint4*)(AL + r * LD + c8 * 8) = *(const uint4*)(Al + (size_t)(m0 + r) * KD + c8 * 8);
            *(uint4*)(BH + r * LD + c8 * 8) = *(const uint4*)(Wh + (size_t)r * KD + c8 * 8);
            *(uint4*)(BL + r * LD + c8 * 8) = *(const uint4*)(Wl + (size_t)r * KD + c8 * 8);
        }
        __syncthreads();

        if (dir == 0) {
#pragma unroll
            for (int mt = 0; mt < 2; mt++)
#pragma unroll
                for (int nt = 0; nt < 4; nt++)
                    wmma::load_matrix_sync(acc[mt][nt], BI + n_off + nt * 16, 128,
                                           wmma::mem_row_major);
        }

#pragma unroll
        for (int ks = 0; ks < KD / 16; ks++) {
            const int k0 = ks * 16;
            wmma::fragment<wmma::matrix_a, 16, 16, 16, __nv_bfloat16, wmma::row_major> ah[2], al[2];
            wmma::fragment<wmma::matrix_b, 16, 16, 16, __nv_bfloat16, wmma::col_major> bh[4], bl[4];
#pragma unroll
            for (int mt = 0; mt < 2; mt++) {
                wmma::load_matrix_sync(ah[mt], AH + (m_off + mt * 16) * LD + k0, LD);
                wmma::load_matrix_sync(al[mt], AL + (m_off + mt * 16) * LD + k0, LD);
            }
#pragma unroll
            for (int nt = 0; nt < 4; nt++) {
                wmma::load_matrix_sync(bh[nt], BH + (n_off + nt * 16) * LD + k0, LD);
                wmma::load_matrix_sync(bl[nt], BL + (n_off + nt * 16) * LD + k0, LD);
            }
#pragma unroll
            for (int mt = 0; mt < 2; mt++)
#pragma unroll
                for (int nt = 0; nt < 4; nt++) {
                    wmma::mma_sync(acc[mt][nt], ah[mt], bh[nt], acc[mt][nt]);
                    wmma::mma_sync(acc[mt][nt], ah[mt], bl[nt], acc[mt][nt]);
                    wmma::mma_sync(acc[mt][nt], al[mt], bh[nt], acc[mt][nt]);
                }
        }
    }

    if (!SPLIT_OUT) {
#pragma unroll
        for (int mt = 0; mt < 2; mt++)
#pragma unroll
            for (int nt = 0; nt < 4; nt++)
                wmma::store_matrix_sync(
                    C + (size_t)(m0 + m_off + mt * 16) * 128 + n_off + nt * 16,
                    acc[mt][nt], 128, wmma::mem_row_major);
    } else {
        float* SF = (float*)smem;
        __syncthreads();
#pragma unroll
        for (int mt = 0; mt < 2; mt++)
#pragma unroll
            for (int nt = 0; nt < 4; nt++)
                wmma::store_matrix_sync(
                    SF + (m_off + mt * 16) * 128 + n_off + nt * 16,
                    acc[mt][nt], 128, wmma::mem_row_major);
        __syncthreads();
#pragma unroll
        for (int t = 0; t < 32; t++) {
            int i = tid + t * 256;
            float2 v = *(const float2*)(SF + i * 2);
            __nv_bfloat16 hx, lx, hy, ly;
            split_bf16(v.x, hx, lx); split_bf16(v.y, hy, ly);
            int r = i >> 6, cc = (i & 63) * 2;
            size_t p = (size_t)(m0 + r) * 128 + cc;
            *(__nv_bfloat162*)(Chi + p) = __nv_bfloat162(hx, hy);
            *(__nv_bfloat162*)(Clo + p) = __nv_bfloat162(lx, ly);
        }
    }
}

// ---------------- prep: all weight images + bias sums ----------------------------
__global__ void prep_kernel(const float* __restrict__ Whh, const float* __restrict__ Wp,
                            const float* __restrict__ Wih, const float* __restrict__ bih,
                            const float* __restrict__ bhh,
                            const float* __restrict__ W0s, const float* __restrict__ W0d,
                            const float* __restrict__ W1s, const float* __restrict__ W1d,
                            const float* __restrict__ b0s, const float* __restrict__ b0d,
                            const float* __restrict__ b1s, const float* __restrict__ b1d) {
    int i = blockIdx.x * blockDim.x + threadIdx.x;
    if (i < 512 * 128) {
        split_bf16(Wih[i], d_wihhi[i], d_wihlo[i]);
        split_bf16(Whh[i], d_whhhi[i], d_whhlo[i]);
    }
    if (i < 128 * 64) {
        split_bf16(0.5f * W0s[i], d_w0sh[i], d_w0sl[i]);
        split_bf16(0.5f * W0d[i], d_w0dh[i], d_w0dl[i]);
        split_bf16(Wp[i], d_wphi[i], d_wplo[i]);
    }
    if (i < 128 * 128) {
        split_bf16(0.5f * W1s[i], d_w1sh[i], d_w1sl[i]);
        split_bf16(0.5f * W1d[i], d_w1dh[i], d_w1dl[i]);
    }
    if (i < 512) d_bsum[i] = bih[i] + bhh[i];
    if (i < 128) {
        d_b0v[i] = 0.5f * (b0s[i] + b0d[i]);
        d_b1v[i] = 0.5f * (b1s[i] + b1d[i]);
    }
}

// ---------------- gx GEMM via WMMA bf16x3 (round-10 winner, unchanged) -----------
#define LDAB 136
#define SM_AH 0
#define SM_AL (128 * LDAB * 2)
#define SM_BH (2 * 128 * LDAB * 2)
#define SM_BL (3 * 128 * LDAB * 2)
#define SM_BI (4 * 128 * LDAB * 2)
#define GX_SMEM (4 * 128 * LDAB * 2 + 16 * 128 * 4)

__global__ void __launch_bounds__(256)
gx_wmma_kernel(float* __restrict__ gx)
{
    extern __shared__ char smem[];
    __nv_bfloat16* AH = (__nv_bfloat16*)(smem + SM_AH);
    __nv_bfloat16* AL = (__nv_bfloat16*)(smem + SM_AL);
    __nv_bfloat16* BH = (__nv_bfloat16*)(smem + SM_BH);
    __nv_bfloat16* BL = (__nv_bfloat16*)(smem + SM_BL);
    float*         BI = (float*)(smem + SM_BI);

    const int tid = threadIdx.x;
    const int wid = tid >> 5;
    const int m0  = blockIdx.x * 128;
    const int m_off = (wid >> 1) * 32;
    const int n_off = (wid & 1) * 64;

#pragma unroll
    for (int t = 0; t < 8; t++) {
        int ch = tid + t * 256;
        int r  = ch >> 4;
        int c16 = ch & 15;
        size_t gsrc = (size_t)(m0 + r) * 128 + c16 * 8;
        *(uint4*)(AH + r * LDAB + c16 * 8) = *(const uint4*)(d_h1hi + gsrc);
        *(uint4*)(AL + r * LDAB + c16 * 8) = *(const uint4*)(d_h1lo + gsrc);
    }

    for (int q = 0; q < 4; q++) {
        __syncthreads();
#pragma unroll
        for (int t = 0; t < 8; t++) {
            int ch = tid + t * 256;
            int r  = ch >> 4;
            int c16 = ch & 15;
            size_t gsrc = (size_t)(q * 128 + r) * 128 + c16 * 8;
            *(uint4*)(BH + r * LDAB + c16 * 8) = *(const uint4*)(d_wihhi + gsrc);
            *(uint4*)(BL + r * LDAB + c16 * 8) = *(const uint4*)(d_wihlo + gsrc);
        }
#pragma unroll
        for (int t = 0; t < 8; t++) {
            int i = tid + t * 256;
            BI[i] = d_bsum[q * 128 + (i & 127)];
        }
        __syncthreads();

        wmma::fragment<wmma::accumulator, 16, 16, 16, float> acc[2][4];
#pragma unroll
        for (int mt = 0; mt < 2; mt++)
#pragma unroll
            for (int nt = 0; nt < 4; nt++)
                wmma::load_matrix_sync(acc[mt][nt], BI + n_off + nt * 16, 128,
                                       wmma::mem_row_major);

#pragma unroll
        for (int ks = 0; ks < 8; ks++) {
            const int k0 = ks * 16;
            wmma::fragment<wmma::matrix_a, 16, 16, 16, __nv_bfloat16, wmma::row_major> ah[2], al[2];
            wmma::fragment<wmma::matrix_b, 16, 16, 16, __nv_bfloat16, wmma::col_major> bh[4], bl[4];
#pragma unroll
            for (int mt = 0; mt < 2; mt++) {
                wmma::load_matrix_sync(ah[mt], AH + (m_off + mt * 16) * LDAB + k0, LDAB);
                wmma::load_matrix_sync(al[mt], AL + (m_off + mt * 16) * LDAB + k0, LDAB);
            }
#pragma unroll
            for (int nt = 0; nt < 4; nt++) {
                wmma::load_matrix_sync(bh[nt], BH + (n_off + nt * 16) * LDAB + k0, LDAB);
                wmma::load_matrix_sync(bl[nt], BL + (n_off + nt * 16) * LDAB + k0, LDAB);
            }
#pragma unroll
            for (int mt = 0; mt < 2; mt++)
#pragma unroll
                for (int nt = 0; nt < 4; nt++) {
                    wmma::mma_sync(acc[mt][nt], ah[mt], bh[nt], acc[mt][nt]);
                    wmma::mma_sync(acc[mt][nt], ah[mt], bl[nt], acc[mt][nt]);
                    wmma::mma_sync(acc[mt][nt], al[mt], bh[nt], acc[mt][nt]);
                }
        }

#pragma unroll
        for (int mt = 0; mt < 2; mt++)
#pragma unroll
            for (int nt = 0; nt < 4; nt++)
                wmma::store_matrix_sync(
                    gx + (size_t)(m0 + m_off + mt * 16) * 512 + q * 128 + n_off + nt * 16,
                    acc[mt][nt], 512, wmma::mem_row_major);
    }
}

// ---------------- LSTM recurrence via WMMA bf16x3 + fused projection -------------
// 64 rows/block (250 blocks), 256 threads. Gate order f,i,g,o; 3-term split MMA.
#define LROW 64
#define LLD  136
#define LS_HHI 0
#define LS_HLO (LROW * LLD * 2)
#define LS_WS  (2 * LROW * LLD * 2)             // 34816: W-gate hi/lo region (69632 B)
#define LS_I   (LS_WS + 2 * 128 * LLD * 2)      // 104448
#define LS_C   (LS_I + LROW * 128 * 4)          // 137216
#define LSTM_SMEM (LS_C + LROW * 128 * 4)       // 169984

__global__ void __launch_bounds__(256)
lstm_wmma_kernel(const float* __restrict__ gx, float* __restrict__ out,
                 const float* __restrict__ bp)
{
    extern __shared__ char sm[];
    __nv_bfloat16* HHI = (__nv_bfloat16*)(sm + LS_HHI);
    __nv_bfloat16* HLO = (__nv_bfloat16*)(sm + LS_HLO);
    __nv_bfloat16* WH  = (__nv_bfloat16*)(sm + LS_WS);
    __nv_bfloat16* WL  = WH + 128 * LLD;
    float*         GB  = (float*)(sm + LS_WS);   // reuse after MMA
    float*         I   = (float*)(sm + LS_I);
    float*         C   = (float*)(sm + LS_C);

    const int tid  = threadIdx.x;
    const int wid  = tid >> 5;
    const int row0 = blockIdx.x * LROW;
    const int mt   = wid >> 1;       // 0..3 -> rows mt*16..+15
    const int nh   = wid & 1;        // n half: cols nh*64 + j*16

    // zero c
#pragma unroll
    for (int k = 0; k < 32; k++) C[tid + k * 256] = 0.f;

    const int gorder[4] = {1, 0, 2, 3};   // f, i, g, o (pytorch cols i,f,g,o)

    for (int t = 0; t < STEPS; t++) {
        for (int gi = 0; gi < 4; gi++) {
            const int gate = gorder[gi];
            __syncthreads();            // WS free; h writes from prev step visible
            if (t > 0) {
#pragma unroll
                for (int k = 0; k < 8; k++) {   // stage W-gate hi/lo [128][LLD]
                    int ch = tid + k * 256;
                    int r  = ch >> 4;
                    int c16 = ch & 15;
                    size_t gsrc = (size_t)(gate * 128 + r) * 128 + c16 * 8;
                    *(uint4*)(WH + r * LLD + c16 * 8) = *(const uint4*)(d_whhhi + gsrc);
                    *(uint4*)(WL + r * LLD + c16 * 8) = *(const uint4*)(d_whhlo + gsrc);
                }
            }
            __syncthreads();

            wmma::fragment<wmma::accumulator, 16, 16, 16, float> acc[4];
#pragma unroll
            for (int j = 0; j < 4; j++)   // seed from gx (row stride 8*512)
                wmma::load_matrix_sync(acc[j],
                    gx + ((size_t)(row0 + mt * 16) * STEPS + t) * 512
                       + gate * 128 + nh * 64 + j * 16,
                    STEPS * 512, wmma::mem_row_major);

            if (t > 0) {
#pragma unroll
                for (int ks = 0; ks < 8; ks++) {
                    const int k0 = ks * 16;
                    wmma::fragment<wmma::matrix_a, 16, 16, 16, __nv_bfloat16, wmma::row_major> ah, al;
                    wmma::fragment<wmma::matrix_b, 16, 16, 16, __nv_bfloat16, wmma::col_major> bh[4], bl[4];
                    wmma::load_matrix_sync(ah, HHI + (mt * 16) * LLD + k0, LLD);
                    wmma::load_matrix_sync(al, HLO + (mt * 16) * LLD + k0, LLD);
#pragma unroll
                    for (int j = 0; j < 4; j++) {
                        wmma::load_matrix_sync(bh[j], WH + (nh * 64 + j * 16) * LLD + k0, LLD);
                        wmma::load_matrix_sync(bl[j], WL + (nh * 64 + j * 16) * LLD + k0, LLD);
                    }
#pragma unroll
                    for (int j = 0; j < 4; j++) {
                        wmma::mma_sync(acc[j], ah, bh[j], acc[j]);
                        wmma::mma_sync(acc[j], ah, bl[j], acc[j]);
                        wmma::mma_sync(acc[j], al, bh[j], acc[j]);
                    }
                }
            }
            __syncthreads();            // all MMA reads of WS done
#pragma unroll
            for (int j = 0; j < 4; j++)
                wmma::store_matrix_sync(GB + (mt * 16) * 128 + nh * 64 + j * 16,
                                        acc[j], 128, wmma::mem_row_major);
            __syncthreads();

            // elementwise
            if (gi == 0) {              // f: c *= sigmoid(f)
#pragma unroll
                for (int k = 0; k < 32; k++) {
                    int i0 = tid + k * 256;
                    C[i0] = sigmoidf_(GB[i0]) * C[i0];
                }
            } else if (gi == 1) {       // i
#pragma unroll
                for (int k = 0; k < 32; k++) {
                    int i0 = tid + k * 256;
                    I[i0] = sigmoidf_(GB[i0]);
                }
            } else if (gi == 2) {       // g: c += sigmoid(i)*tanh(g)
#pragma unroll
                for (int k = 0; k < 32; k++) {
                    int i0 = tid + k * 256;
                    C[i0] += I[i0] * tanhf(GB[i0]);
                }
            } else {                    // o: h = sigmoid(o)*tanh(c), split to smem
#pragma unroll
                for (int k = 0; k < 16; k++) {
                    int i2  = tid + k * 256;     // float2 index
                    int idx = i2 * 2;
                    float h0v = sigmoidf_(GB[idx])     * tanhf(C[idx]);
                    float h1v = sigmoidf_(GB[idx + 1]) * tanhf(C[idx + 1]);
                    __nv_bfloat16 h0h, h0l, h1h, h1l;
                    split_bf16(h0v, h0h, h0l);
                    split_bf16(h1v, h1h, h1l);
                    int r = idx >> 7, cc = idx & 127;
                    *(__nv_bfloat162*)(HHI + r * LLD + cc) = __nv_bfloat162(h0h, h1h);
                    *(__nv_bfloat162*)(HLO + r * LLD + cc) = __nv_bfloat162(h0l, h1l);
                }
            }
        }
    }

    // ---- projection: out[row][0..63] = h @ Wp^T + bp, bf16x3 ----
    __syncthreads();
    __nv_bfloat16* WPH = (__nv_bfloat16*)(sm + LS_WS);
    __nv_bfloat16* WPL = WPH + 64 * LLD;
    float* BIAS = (float*)(sm + LS_WS + 2 * 64 * LLD * 2);   // 16x64 fp32
#pragma unroll
    for (int k = 0; k < 4; k++) {        // stage Wp hi/lo [64][LLD]
        int ch = tid + k * 256;
        int r  = ch >> 4;
        int c16 = ch & 15;
        size_t gsrc = (size_t)r * 128 + c16 * 8;
        *(uint4*)(WPH + r * LLD + c16 * 8) = *(const uint4*)(d_wphi + gsrc);
        *(uint4*)(WPL + r * LLD + c16 * 8) = *(const uint4*)(d_wplo + gsrc);
    }
#pragma unroll
    for (int k = 0; k < 4; k++) {        // bias tile 16x64 replicated
        int i0 = tid + k * 256;
        BIAS[i0] = bp[i0 & 63];
    }
    __syncthreads();

    const int np = wid & 1;              // col half: np*32 + j*16
    wmma::fragment<wmma::accumulator, 16, 16, 16, float> pacc[2];
#pragma unroll
    for (int j = 0; j < 2; j++)
        wmma::load_matrix_sync(pacc[j], BIAS + np * 32 + j * 16, 64, wmma::mem_row_major);
#pragma unroll
    for (int ks = 0; ks < 8; ks++) {
        const int k0 = ks * 16;
        wmma::fragment<wmma::matrix_a, 16, 16, 16, __nv_bfloat16, wmma::row_major> ah, al;
        wmma::fragment<wmma::matrix_b, 16, 16, 16, __nv_bfloat16, wmma::col_major> bh[2], bl[2];
        wmma::load_matrix_sync(ah, HHI + (mt * 16) * LLD + k0, LLD);
        wmma::load_matrix_sync(al, HLO + (mt * 16) * LLD + k0, LLD);
#pragma unroll
        for (int j = 0; j < 2; j++) {
            wmma::load_matrix_sync(bh[j], WPH + (np * 32 + j * 16) * LLD + k0, LLD);
            wmma::load_matrix_sync(bl[j], WPL + (np * 32 + j * 16) * LLD + k0, LLD);
        }
#pragma unroll
        for (int j = 0; j < 2; j++) {
            wmma::mma_sync(pacc[j], ah, bh[j], pacc[j]);
            wmma::mma_sync(pacc[j], ah, bl[j], pacc[j]);
            wmma::mma_sync(pacc[j], al, bh[j], pacc[j]);
        }
    }
#pragma unroll
    for (int j = 0; j < 2; j++)
        wmma::store_matrix_sync(out + (size_t)(row0 + mt * 16) * 64 + np * 32 + j * 16,
                                pacc[j], 64, wmma::mem_row_major);
}

// ---------------- launch --------------------------------------------------------
#define GCN_SMEM64  (4 * 128 * 72 * 2 + 16 * 128 * 4)
#define GCN_SMEM128 (4 * 128 * 136 * 2 + 16 * 128 * 4)

extern "C" void kernel_launch(void* const* d_in, const int* in_sizes, int n_in,
                              void* d_out, int out_size)
{
    const float* x_seq = (const float*)d_in[0];
    const int*   ei    = (const int*)  d_in[1];
    const float* ew    = (const float*)d_in[2];
    const float* W0s   = (const float*)d_in[3];
    const float* b0s   = (const float*)d_in[4];
    const float* W0d   = (const float*)d_in[5];
    const float* b0d   = (const float*)d_in[6];
    const float* W1s   = (const float*)d_in[7];
    const float* b1s   = (const float*)d_in[8];
    const float* W1d   = (const float*)d_in[9];
    const float* b1d   = (const float*)d_in[10];
    const float* Wih   = (const float*)d_in[11];
    const float* Whh   = (const float*)d_in[12];
    const float* bih   = (const float*)d_in[13];
    const float* bhh   = (const float*)d_in[14];
    const float* Wp    = (const float*)d_in[15];
    const float* bp    = (const float*)d_in[16];
    float* out = (float*)d_out;

    float *h0, *gx, *b0v, *b1v;
    __nv_bfloat16 *afh, *afl, *abh, *abl, *h1hi, *h1lo;
    __nv_bfloat16 *w0sh, *w0sl, *w0dh, *w0dl, *w1sh, *w1sl, *w1dh, *w1dl;
    cudaGetSymbolAddress((void**)&h0,   d_h0);
    cudaGetSymbolAddress((void**)&gx,   d_gx);
    cudaGetSymbolAddress((void**)&afh,  d_aggfh);
    cudaGetSymbolAddress((void**)&afl,  d_aggfl);
    cudaGetSymbolAddress((void**)&abh,  d_aggbh);
    cudaGetSymbolAddress((void**)&abl,  d_aggbl);
    cudaGetSymbolAddress((void**)&h1hi, d_h1hi);
    cudaGetSymbolAddress((void**)&h1lo, d_h1lo);
    cudaGetSymbolAddress((void**)&w0sh, d_w0sh);
    cudaGetSymbolAddress((void**)&w0sl, d_w0sl);
    cudaGetSymbolAddress((void**)&w0dh, d_w0dh);
    cudaGetSymbolAddress((void**)&w0dl, d_w0dl);
    cudaGetSymbolAddress((void**)&w1sh, d_w1sh);
    cudaGetSymbolAddress((void**)&w1sl, d_w1sl);
    cudaGetSymbolAddress((void**)&w1dh, d_w1dh);
    cudaGetSymbolAddress((void**)&w1dl, d_w1dl);
    cudaGetSymbolAddress((void**)&b0v,  d_b0v);
    cudaGetSymbolAddress((void**)&b1v,  d_b1v);

    cudaFuncSetAttribute(gx_wmma_kernel,
                         cudaFuncAttributeMaxDynamicSharedMemorySize, GX_SMEM);
    cudaFuncSetAttribute((const void*)gcn_wmma_kernel<64, false>,
                         cudaFuncAttributeMaxDynamicSharedMemorySize, GCN_SMEM64);
    cudaFuncSetAttribute((const void*)gcn_wmma_kernel<128, true>,
                         cudaFuncAttributeMaxDynamicSharedMemorySize, GCN_SMEM128);
    cudaFuncSetAttribute(lstm_wmma_kernel,
                         cudaFuncAttributeMaxDynamicSharedMemorySize, LSTM_SMEM);

    const int M = Gn * NN;   // 128000

    // ---- CSR build + weight prep ----
    zero_kernel<<<(Gn * NN + 255) / 256, 256>>>();
    degcnt_kernel<<<(Gn * EE + 255) / 256, 256>>>(ei, ew);
    inv_kernel<<<(Gn * NN + 255) / 256, 256>>>();
    scan_kernel<<<dim3(Gn, 2), 1024>>>();
    scatter_kernel<<<(Gn * EE + 255) / 256, 256>>>(ei, ew);
    prep_kernel<<<256, 256>>>(Whh, Wp, Wih, bih, bhh,
                              W0s, W0d, W1s, W1d, b0s, b0d, b1s, b1d);

    const int gblocks = (Gn * NN * 2 * 32 + 255) / 256;

    // ---- GCN layer 0 (F=64 -> H=128) ----
    gather_kernel<64><<<gblocks, 256>>>(x_seq);
    gcn_wmma_kernel<64, false><<<M / 128, 256, GCN_SMEM64>>>(
        afh, afl, abh, abl, w0sh, w0sl, w0dh, w0dl, b0v, h0, nullptr, nullptr);

    // ---- GCN layer 1 (H=128 -> H=128) -> h1 bf16 hi/lo ----
    gather_kernel<128><<<gblocks, 256>>>(h0);
    gcn_wmma_kernel<128, true><<<M / 128, 256, GCN_SMEM128>>>(
        afh, afl, abh, abl, w1sh, w1sl, w1dh, w1dl, b1v, nullptr, h1hi, h1lo);

    // ---- LSTM input GEMM via WMMA bf16x3 ----
    gx_wmma_kernel<<<M / 128, 256, GX_SMEM>>>(gx);

    // ---- LSTM recurrence + projection via WMMA bf16x3 ----
    lstm_wmma_kernel<<<BNR / LROW, 256, LSTM_SMEM>>>(gx, out, bp);
}

// round 15
// speedup vs baseline: 1.3964x; 1.3964x over previous
#include <cuda_runtime.h>
#include <cuda_bf16.h>
#include <mma.h>

using namespace nvcuda;

// Problem dims (fixed by the reference)
#define Gn   32
#define NN   4000
#define EE   32000
#define FD0  64
#define HD   128
#define BNR  16000
#define STEPS 8

typedef unsigned long long u64;

__device__ __forceinline__ u64 fma2(u64 a, u64 b, u64 c) {
    u64 d;
    asm("fma.rn.f32x2 %0, %1, %2, %3;" : "=l"(d) : "l"(a), "l"(b), "l"(c));
    return d;
}
__device__ __forceinline__ u64 pack2(float x) {
    u64 d; asm("mov.b64 %0, {%1, %1};" : "=l"(d) : "f"(x)); return d;
}
__device__ __forceinline__ void split_bf16(float v, __nv_bfloat16& hi, __nv_bfloat16& lo) {
    hi = __float2bfloat16(v);
    lo = __float2bfloat16(v - __bfloat162float(hi));
}
__device__ __forceinline__ float sigmoidf_(float x) { return 1.f / (1.f + __expf(-x)); }

// ---------------- scratch (device globals) --------------------------------------
__device__ float d_deg_out[Gn * NN];
__device__ float d_deg_in [Gn * NN];
__device__ int   d_cnt_f[Gn * NN];
__device__ int   d_cnt_b[Gn * NN];
__device__ int   d_off_f[Gn * NN];
__device__ int   d_off_b[Gn * NN];
__device__ int   d_cur_f[Gn * NN];
__device__ int   d_cur_b[Gn * NN];
__device__ int   d_csr_if[Gn * EE];
__device__ float d_csr_wf[Gn * EE];
__device__ int   d_csr_ib[Gn * EE];
__device__ float d_csr_wb[Gn * EE];
// aggregation outputs, bf16 hi/lo
__device__ __nv_bfloat16 d_aggfh[(size_t)Gn * NN * HD];
__device__ __nv_bfloat16 d_aggfl[(size_t)Gn * NN * HD];
__device__ __nv_bfloat16 d_aggbh[(size_t)Gn * NN * HD];
__device__ __nv_bfloat16 d_aggbl[(size_t)Gn * NN * HD];
__device__ float d_h0    [(size_t)Gn * NN * HD];
__device__ float d_gx    [(size_t)BNR * STEPS * 4 * HD];
__device__ float d_whhT  [HD * 4 * HD];   // Whh^T [128][512]
__device__ float d_wpT   [HD * FD0];      // Wp^T  [128][64]
// bf16x3 weight/input images
__device__ __nv_bfloat16 d_h1hi[(size_t)Gn * NN * HD];
__device__ __nv_bfloat16 d_h1lo[(size_t)Gn * NN * HD];
__device__ __nv_bfloat16 d_wihhi[512 * 128];
__device__ __nv_bfloat16 d_wihlo[512 * 128];
__device__ float d_bsum[512];             // bih + bhh
__device__ __nv_bfloat16 d_w0sh[HD * FD0], d_w0sl[HD * FD0];
__device__ __nv_bfloat16 d_w0dh[HD * FD0], d_w0dl[HD * FD0];
__device__ __nv_bfloat16 d_w1sh[HD * HD],  d_w1sl[HD * HD];
__device__ __nv_bfloat16 d_w1dh[HD * HD],  d_w1dl[HD * HD];
__device__ float d_b0v[HD];
__device__ float d_b1v[HD];

// ---------------- CSR build ------------------------------------------------------
__global__ void zero_kernel() {
    int i = blockIdx.x * blockDim.x + threadIdx.x;
    if (i < Gn * NN) {
        d_deg_out[i] = 0.f; d_deg_in[i] = 0.f;
        d_cnt_f[i] = 0;     d_cnt_b[i] = 0;
    }
}

__global__ void degcnt_kernel(const int* __restrict__ ei, const float* __restrict__ ew) {
    int i = blockIdx.x * blockDim.x + threadIdx.x;
    if (i >= Gn * EE) return;
    int g = i / EE, e = i - g * EE;
    const int* eig = ei + (size_t)g * 2 * EE;
    int src = eig[e], dst = eig[EE + e];
    float w = ew[i];
    atomicAdd(&d_deg_out[g * NN + src], w);
    atomicAdd(&d_deg_in [g * NN + dst], w);
    atomicAdd(&d_cnt_f[g * NN + dst], 1);
    atomicAdd(&d_cnt_b[g * NN + src], 1);
}

__global__ void inv_kernel() {
    int i = blockIdx.x * blockDim.x + threadIdx.x;
    if (i >= Gn * NN) return;
    float v = d_deg_out[i];
    d_deg_out[i] = (v > 0.f) ? rsqrtf(fmaxf(v, 1e-12f)) : 0.f;
    v = d_deg_in[i];
    d_deg_in[i]  = (v > 0.f) ? rsqrtf(fmaxf(v, 1e-12f)) : 0.f;
}

__global__ void __launch_bounds__(1024) scan_kernel() {
    int g   = blockIdx.x;
    int dir = blockIdx.y;
    const int* cnt = dir ? d_cnt_b : d_cnt_f;
    int* off = dir ? d_off_b : d_off_f;
    int* cur = dir ? d_cur_b : d_cur_f;
    int tid = threadIdx.x;
    int base = g * NN;
    int v[4], tot = 0;
#pragma unroll
    for (int k = 0; k < 4; k++) {
        int i = tid * 4 + k;
        v[k] = (i < NN) ? cnt[base + i] : 0;
        tot += v[k];
    }
    __shared__ int s[1024];
    s[tid] = tot;
    __syncthreads();
    for (int d = 1; d < 1024; d <<= 1) {
        int t = (tid >= d) ? s[tid - d] : 0;
        __syncthreads();
        s[tid] += t;
        __syncthreads();
    }
    int ex = s[tid] - tot;
#pragma unroll
    for (int k = 0; k < 4; k++) {
        int i = tid * 4 + k;
        if (i < NN) { off[base + i] = ex; cur[base + i] = ex; ex += v[k]; }
    }
}

__global__ void scatter_kernel(const int* __restrict__ ei, const float* __restrict__ ew) {
    int i = blockIdx.x * blockDim.x + threadIdx.x;
    if (i >= Gn * EE) return;
    int g = i / EE, e = i - g * EE;
    const int* eig = ei + (size_t)g * 2 * EE;
    int src = eig[e], dst = eig[EE + e];
    float w = ew[i] * d_deg_out[g * NN + src] * d_deg_in[g * NN + dst];
    int pf = atomicAdd(&d_cur_f[g * NN + dst], 1);
    d_csr_if[g * EE + pf] = src;
    d_csr_wf[g * EE + pf] = w;
    int pb = atomicAdd(&d_cur_b[g * NN + src], 1);
    d_csr_ib[g * EE + pb] = dst;
    d_csr_wb[g * EE + pb] = w;
}

// ---------------- gather aggregation (round-13, unchanged) -----------------------
template<int FD>
__global__ void __launch_bounds__(256) gather_kernel(const float* __restrict__ x) {
    int gw = (blockIdx.x * 256 + threadIdx.x) >> 5;
    int lane = threadIdx.x & 31;
    if (gw >= Gn * NN * 2) return;
    int dir = gw & 1;
    int gn  = gw >> 1;
    int g   = gn / NN;
    const int*   off = dir ? d_off_b : d_off_f;
    const int*   cnt = dir ? d_cnt_b : d_cnt_f;
    const int*   nb  = dir ? d_csr_ib : d_csr_if;
    const float* wv  = dir ? d_csr_wb : d_csr_wf;
    __nv_bfloat16* oh = dir ? d_aggbh : d_aggfh;
    __nv_bfloat16* ol = dir ? d_aggbl : d_aggfl;
    int o = off[gn], c = cnt[gn];
    const float* xg = x + (size_t)g * NN * FD;
    const int ebase = g * EE + o;

    if (FD == 128) {
        float4 acc = make_float4(0.f, 0.f, 0.f, 0.f);
        int j = 0;
        for (; j + 4 <= c; j += 4) {
            int   s0 = nb[ebase + j],     s1 = nb[ebase + j + 1];
            int   s2 = nb[ebase + j + 2], s3 = nb[ebase + j + 3];
            float w0 = wv[ebase + j],     w1 = wv[ebase + j + 1];
            float w2 = wv[ebase + j + 2], w3 = wv[ebase + j + 3];
            float4 x0 = *(const float4*)(xg + (size_t)s0 * FD + lane * 4);
            float4 x1 = *(const float4*)(xg + (size_t)s1 * FD + lane * 4);
            float4 x2 = *(const float4*)(xg + (size_t)s2 * FD + lane * 4);
            float4 x3 = *(const float4*)(xg + (size_t)s3 * FD + lane * 4);
            acc.x += w0 * x0.x; acc.y += w0 * x0.y; acc.z += w0 * x0.z; acc.w += w0 * x0.w;
            acc.x += w1 * x1.x; acc.y += w1 * x1.y; acc.z += w1 * x1.z; acc.w += w1 * x1.w;
            acc.x += w2 * x2.x; acc.y += w2 * x2.y; acc.z += w2 * x2.z; acc.w += w2 * x2.w;
            acc.x += w3 * x3.x; acc.y += w3 * x3.y; acc.z += w3 * x3.z; acc.w += w3 * x3.w;
        }
        for (; j < c; j++) {
            int   s = nb[ebase + j];
            float w = wv[ebase + j];
            float4 xv = *(const float4*)(xg + (size_t)s * FD + lane * 4);
            acc.x += w * xv.x; acc.y += w * xv.y;
            acc.z += w * xv.z; acc.w += w * xv.w;
        }
        __nv_bfloat16 hx, lx, hy, ly, hz, lz, hw, lw;
        split_bf16(acc.x, hx, lx); split_bf16(acc.y, hy, ly);
        split_bf16(acc.z, hz, lz); split_bf16(acc.w, hw, lw);
        size_t p = (size_t)gn * FD + lane * 4;
        *(__nv_bfloat162*)(oh + p)     = __nv_bfloat162(hx, hy);
        *(__nv_bfloat162*)(oh + p + 2) = __nv_bfloat162(hz, hw);
        *(__nv_bfloat162*)(ol + p)     = __nv_bfloat162(lx, ly);
        *(__nv_bfloat162*)(ol + p + 2) = __nv_bfloat162(lz, lw);
    } else {
        float2 acc = make_float2(0.f, 0.f);
        int j = 0;
        for (; j + 4 <= c; j += 4) {
            int   s0 = nb[ebase + j],     s1 = nb[ebase + j + 1];
            int   s2 = nb[ebase + j + 2], s3 = nb[ebase + j + 3];
            float w0 = wv[ebase + j],     w1 = wv[ebase + j + 1];
            float w2 = wv[ebase + j + 2], w3 = wv[ebase + j + 3];
            float2 x0 = *(const float2*)(xg + (size_t)s0 * FD + lane * 2);
            float2 x1 = *(const float2*)(xg + (size_t)s1 * FD + lane * 2);
            float2 x2 = *(const float2*)(xg + (size_t)s2 * FD + lane * 2);
            float2 x3 = *(const float2*)(xg + (size_t)s3 * FD + lane * 2);
            acc.x += w0 * x0.x; acc.y += w0 * x0.y;
            acc.x += w1 * x1.x; acc.y += w1 * x1.y;
            acc.x += w2 * x2.x; acc.y += w2 * x2.y;
            acc.x += w3 * x3.x; acc.y += w3 * x3.y;
        }
        for (; j < c; j++) {
            int   s = nb[ebase + j];
            float w = wv[ebase + j];
            float2 xv = *(const float2*)(xg + (size_t)s * FD + lane * 2);
            acc.x += w * xv.x; acc.y += w * xv.y;
        }
        __nv_bfloat16 hx, lx, hy, ly;
        split_bf16(acc.x, hx, lx); split_bf16(acc.y, hy, ly);
        size_t p = (size_t)gn * FD + lane * 2;
        *(__nv_bfloat162*)(oh + p) = __nv_bfloat162(hx, hy);
        *(__nv_bfloat162*)(ol + p) = __nv_bfloat162(lx, ly);
    }
}

// ---------------- GCN dual GEMM via WMMA bf16x3 (round-13, unchanged) ------------
template<int KD, bool SPLIT_OUT>
__global__ void __launch_bounds__(256)
gcn_wmma_kernel(const __nv_bfloat16* __restrict__ A0h, const __nv_bfloat16* __restrict__ A0l,
                const __nv_bfloat16* __restrict__ A1h, const __nv_bfloat16* __restrict__ A1l,
                const __nv_bfloat16* __restrict__ W0h, const __nv_bfloat16* __restrict__ W0l,
                const __nv_bfloat16* __restrict__ W1h, const __nv_bfloat16* __restrict__ W1l,
                const float* __restrict__ bias, float* __restrict__ C,
                __nv_bfloat16* __restrict__ Chi, __nv_bfloat16* __restrict__ Clo)
{
    constexpr int LD = KD + 8;
    extern __shared__ char smem[];
    __nv_bfloat16* AH = (__nv_bfloat16*)smem;
    __nv_bfloat16* AL = AH + 128 * LD;
    __nv_bfloat16* BH = AL + 128 * LD;
    __nv_bfloat16* BL = BH + 128 * LD;
    float*         BI = (float*)(BL + 128 * LD);

    const int tid = threadIdx.x;
    const int wid = tid >> 5;
    const int m0  = blockIdx.x * 128;
    const int m_off = (wid >> 1) * 32;
    const int n_off = (wid & 1) * 64;
    constexpr int CPR = KD / 8;

#pragma unroll
    for (int t = 0; t < 8; t++) {
        int i = tid + t * 256;
        BI[i] = bias[i & 127];
    }

    wmma::fragment<wmma::accumulator, 16, 16, 16, float> acc[2][4];

    for (int dir = 0; dir < 2; dir++) {
        const __nv_bfloat16* Ah = dir ? A1h : A0h;
        const __nv_bfloat16* Al = dir ? A1l : A0l;
        const __nv_bfloat16* Wh = dir ? W1h : W0h;
        const __nv_bfloat16* Wl = dir ? W1l : W0l;
        if (dir) __syncthreads();
#pragma unroll
        for (int t = 0; t < KD / 16; t++) {
            int ch = tid + t * 256;
            int r  = ch / CPR;
            int c8 = ch % CPR;
            *(uint4*)(AH + r * LD + c8 * 8) = *(const uint4*)(Ah + (size_t)(m0 + r) * KD + c8 * 8);
            *(uint4*)(AL + r * LD + c8 * 8) = *(const uint4*)(Al + (size_t)(m0 + r) * KD + c8 * 8);
            *(uint4*)(BH + r * LD + c8 * 8) = *(const uint4*)(Wh + (size_t)r * KD + c8 * 8);
            *(uint4*)(BL + r * LD + c8 * 8) = *(const uint4*)(Wl + (size_t)r * KD + c8 * 8);
        }
        __syncthreads();

        if (dir == 0) {
#pragma unroll
            for (int mt = 0; mt < 2; mt++)
#pragma unroll
                for (int nt = 0; nt < 4; nt++)
                    wmma::load_matrix_sync(acc[mt][nt], BI + n_off + nt * 16, 128,
                                           wmma::mem_row_major);
        }

#pragma unroll
        for (int ks = 0; ks < KD / 16; ks++) {
            const int k0 = ks * 16;
            wmma::fragment<wmma::matrix_a, 16, 16, 16, __nv_bfloat16, wmma::row_major> ah[2], al[2];
            wmma::fragment<wmma::matrix_b, 16, 16, 16, __nv_bfloat16, wmma::col_major> bh[4], bl[4];
#pragma unroll
            for (int mt = 0; mt < 2; mt++) {
                wmma::load_matrix_sync(ah[mt], AH + (m_off + mt * 16) * LD + k0, LD);
                wmma::load_matrix_sync(al[mt], AL + (m_off + mt * 16) * LD + k0, LD);
            }
#pragma unroll
            for (int nt = 0; nt < 4; nt++) {
                wmma::load_matrix_sync(bh[nt], BH + (n_off + nt * 16) * LD + k0, LD);
                wmma::load_matrix_sync(bl[nt], BL + (n_off + nt * 16) * LD + k0, LD);
            }
#pragma unroll
            for (int mt = 0; mt < 2; mt++)
#pragma unroll
                for (int nt = 0; nt < 4; nt++) {
                    wmma::mma_sync(acc[mt][nt], ah[mt], bh[nt], acc[mt][nt]);
                    wmma::mma_sync(acc[mt][nt], ah[mt], bl[nt], acc[mt][nt]);
                    wmma::mma_sync(acc[mt][nt], al[mt], bh[nt], acc[mt][nt]);
                }
        }
    }

    if (!SPLIT_OUT) {
#pragma unroll
        for (int mt = 0; mt < 2; mt++)
#pragma unroll
            for (int nt = 0; nt < 4; nt++)
                wmma::store_matrix_sync(
                    C + (size_t)(m0 + m_off + mt * 16) * 128 + n_off + nt * 16,
                    acc[mt][nt], 128, wmma::mem_row_major);
    } else {
        float* SF = (float*)smem;
        __syncthreads();
#pragma unroll
        for (int mt = 0; mt < 2; mt++)
#pragma unroll
            for (int nt = 0; nt < 4; nt++)
                wmma::store_matrix_sync(
                    SF + (m_off + mt * 16) * 128 + n_off + nt * 16,
                    acc[mt][nt], 128, wmma::mem_row_major);
        __syncthreads();
#pragma unroll
        for (int t = 0; t < 32; t++) {
            int i = tid + t * 256;
            float2 v = *(const float2*)(SF + i * 2);
            __nv_bfloat16 hx, lx, hy, ly;
            split_bf16(v.x, hx, lx); split_bf16(v.y, hy, ly);
            int r = i >> 6, cc = (i & 63) * 2;
            size_t p = (size_t)(m0 + r) * 128 + cc;
            *(__nv_bfloat162*)(Chi + p) = __nv_bfloat162(hx, hy);
            *(__nv_bfloat162*)(Clo + p) = __nv_bfloat162(lx, ly);
        }
    }
}

// ---------------- prep: all weight images + bias sums ----------------------------
__global__ void prep_kernel(const float* __restrict__ Whh, const float* __restrict__ Wp,
                            const float* __restrict__ Wih, const float* __restrict__ bih,
                            const float* __restrict__ bhh,
                            const float* __restrict__ W0s, const float* __restrict__ W0d,
                            const float* __restrict__ W1s, const float* __restrict__ W1d,
                            const float* __restrict__ b0s, const float* __restrict__ b0d,
                            const float* __restrict__ b1s, const float* __restrict__ b1d) {
    int i = blockIdx.x * blockDim.x + threadIdx.x;
    if (i < 512 * 128) {
        int j = i >> 7, k = i & 127;
        d_whhT[(size_t)k * 512 + j] = Whh[i];
        split_bf16(Wih[i], d_wihhi[i], d_wihlo[i]);
    }
    if (i < 128 * 64) {
        split_bf16(0.5f * W0s[i], d_w0sh[i], d_w0sl[i]);
        split_bf16(0.5f * W0d[i], d_w0dh[i], d_w0dl[i]);
    }
    if (i < 128 * 128) {
        split_bf16(0.5f * W1s[i], d_w1sh[i], d_w1sl[i]);
        split_bf16(0.5f * W1d[i], d_w1dh[i], d_w1dl[i]);
    }
    if (i < 64 * 128) {
        int j = i >> 7, k = i & 127;
        d_wpT[k * 64 + j] = Wp[i];
    }
    if (i < 512) d_bsum[i] = bih[i] + bhh[i];
    if (i < 128) {
        d_b0v[i] = 0.5f * (b0s[i] + b0d[i]);
        d_b1v[i] = 0.5f * (b1s[i] + b1d[i]);
    }
}

// ---------------- gx GEMM via WMMA bf16x3 (round-10 winner, unchanged) -----------
#define LDAB 136
#define SM_AH 0
#define SM_AL (128 * LDAB * 2)
#define SM_BH (2 * 128 * LDAB * 2)
#define SM_BL (3 * 128 * LDAB * 2)
#define SM_BI (4 * 128 * LDAB * 2)
#define GX_SMEM (4 * 128 * LDAB * 2 + 16 * 128 * 4)

__global__ void __launch_bounds__(256)
gx_wmma_kernel(float* __restrict__ gx)
{
    extern __shared__ char smem[];
    __nv_bfloat16* AH = (__nv_bfloat16*)(smem + SM_AH);
    __nv_bfloat16* AL = (__nv_bfloat16*)(smem + SM_AL);
    __nv_bfloat16* BH = (__nv_bfloat16*)(smem + SM_BH);
    __nv_bfloat16* BL = (__nv_bfloat16*)(smem + SM_BL);
    float*         BI = (float*)(smem + SM_BI);

    const int tid = threadIdx.x;
    const int wid = tid >> 5;
    const int m0  = blockIdx.x * 128;
    const int m_off = (wid >> 1) * 32;
    const int n_off = (wid & 1) * 64;

#pragma unroll
    for (int t = 0; t < 8; t++) {
        int ch = tid + t * 256;
        int r  = ch >> 4;
        int c16 = ch & 15;
        size_t gsrc = (size_t)(m0 + r) * 128 + c16 * 8;
        *(uint4*)(AH + r * LDAB + c16 * 8) = *(const uint4*)(d_h1hi + gsrc);
        *(uint4*)(AL + r * LDAB + c16 * 8) = *(const uint4*)(d_h1lo + gsrc);
    }

    for (int q = 0; q < 4; q++) {
        __syncthreads();
#pragma unroll
        for (int t = 0; t < 8; t++) {
            int ch = tid + t * 256;
            int r  = ch >> 4;
            int c16 = ch & 15;
            size_t gsrc = (size_t)(q * 128 + r) * 128 + c16 * 8;
            *(uint4*)(BH + r * LDAB + c16 * 8) = *(const uint4*)(d_wihhi + gsrc);
            *(uint4*)(BL + r * LDAB + c16 * 8) = *(const uint4*)(d_wihlo + gsrc);
        }
#pragma unroll
        for (int t = 0; t < 8; t++) {
            int i = tid + t * 256;
            BI[i] = d_bsum[q * 128 + (i & 127)];
        }
        __syncthreads();

        wmma::fragment<wmma::accumulator, 16, 16, 16, float> acc[2][4];
#pragma unroll
        for (int mt = 0; mt < 2; mt++)
#pragma unroll
            for (int nt = 0; nt < 4; nt++)
                wmma::load_matrix_sync(acc[mt][nt], BI + n_off + nt * 16, 128,
                                       wmma::mem_row_major);

#pragma unroll
        for (int ks = 0; ks < 8; ks++) {
            const int k0 = ks * 16;
            wmma::fragment<wmma::matrix_a, 16, 16, 16, __nv_bfloat16, wmma::row_major> ah[2], al[2];
            wmma::fragment<wmma::matrix_b, 16, 16, 16, __nv_bfloat16, wmma::col_major> bh[4], bl[4];
#pragma unroll
            for (int mt = 0; mt < 2; mt++) {
                wmma::load_matrix_sync(ah[mt], AH + (m_off + mt * 16) * LDAB + k0, LDAB);
                wmma::load_matrix_sync(al[mt], AL + (m_off + mt * 16) * LDAB + k0, LDAB);
            }
#pragma unroll
            for (int nt = 0; nt < 4; nt++) {
                wmma::load_matrix_sync(bh[nt], BH + (n_off + nt * 16) * LDAB + k0, LDAB);
                wmma::load_matrix_sync(bl[nt], BL + (n_off + nt * 16) * LDAB + k0, LDAB);
            }
#pragma unroll
            for (int mt = 0; mt < 2; mt++)
#pragma unroll
                for (int nt = 0; nt < 4; nt++) {
                    wmma::mma_sync(acc[mt][nt], ah[mt], bh[nt], acc[mt][nt]);
                    wmma::mma_sync(acc[mt][nt], ah[mt], bl[nt], acc[mt][nt]);
                    wmma::mma_sync(acc[mt][nt], al[mt], bh[nt], acc[mt][nt]);
                }
        }

#pragma unroll
        for (int mt = 0; mt < 2; mt++)
#pragma unroll
            for (int nt = 0; nt < 4; nt++)
                wmma::store_matrix_sync(
                    gx + (size_t)(m0 + m_off + mt * 16) * 512 + q * 128 + n_off + nt * 16,
                    acc[mt][nt], 512, wmma::mem_row_major);
    }
}

// ---------------- LSTM recurrence (FFMA2) + fused projection: 64 rows/block ------
__global__ void __launch_bounds__(512)
lstm_kernel(float* __restrict__ out, const float* __restrict__ bp)
{
    __shared__ float h_s[64][128];     // 32 KB
    __shared__ float w_s[16][512];     // 32 KB; reused as Wp^T [128][64] in epilogue
    const int tid  = threadIdx.x;
    const int tc   = tid & 31;
    const int tr   = tid >> 5;         // 0..15 -> rows tr*4..+3
    const int row0 = blockIdx.x * 64 + tr * 4;

    float c[4][4];
#pragma unroll
    for (int a = 0; a < 4; a++)
#pragma unroll
        for (int b = 0; b < 4; b++) c[a][b] = 0.f;

    for (int t = 0; t < STEPS; t++) {
        u64 acc[4][4][2];   // [gate][row][colpair]
#pragma unroll
        for (int gate = 0; gate < 4; gate++)
#pragma unroll
            for (int ri = 0; ri < 4; ri++) {
                float4 v = *(const float4*)(d_gx +
                    ((size_t)(row0 + ri) * STEPS + t) * 512 + gate * 128 + tc * 4);
                acc[gate][ri][0] = *(const u64*)&v.x;
                acc[gate][ri][1] = *(const u64*)&v.z;
            }

        if (t > 0) {
            for (int kt = 0; kt < 8; kt++) {
                __syncthreads();
#pragma unroll
                for (int i = 0; i < 4; i++) {     // 2048 float4 chunks, 512 thr x 4
                    int q  = tid + i * 512;
                    int kk = q >> 7;
                    int j4 = (q & 127) << 2;
                    *(float4*)&w_s[kk][j4] =
                        *(const float4*)(d_whhT + (size_t)(kt * 16 + kk) * 512 + j4);
                }
                __syncthreads();
#pragma unroll
                for (int kk = 0; kk < 16; kk++) {
                    u64 hp[4];
#pragma unroll
                    for (int ri = 0; ri < 4; ri++)
                        hp[ri] = pack2(h_s[tr * 4 + ri][kt * 16 + kk]);
#pragma unroll
                    for (int gate = 0; gate < 4; gate++) {
                        float4 w = *(const float4*)&w_s[kk][gate * 128 + tc * 4];
                        u64 w01 = *(const u64*)&w.x;
                        u64 w23 = *(const u64*)&w.z;
#pragma unroll
                        for (int ri = 0; ri < 4; ri++) {
                            acc[gate][ri][0] = fma2(hp[ri], w01, acc[gate][ri][0]);
                            acc[gate][ri][1] = fma2(hp[ri], w23, acc[gate][ri][1]);
                        }
                    }
                }
            }
            __syncthreads();
        }

#pragma unroll
        for (int ri = 0; ri < 4; ri++) {
            float2 i01 = *(float2*)&acc[0][ri][0], i23 = *(float2*)&acc[0][ri][1];
            float2 f01 = *(float2*)&acc[1][ri][0], f23 = *(float2*)&acc[1][ri][1];
            float2 g01 = *(float2*)&acc[2][ri][0], g23 = *(float2*)&acc[2][ri][1];
            float2 o01 = *(float2*)&acc[3][ri][0], o23 = *(float2*)&acc[3][ri][1];
            float ig[4] = {i01.x, i01.y, i23.x, i23.y};
            float fg[4] = {f01.x, f01.y, f23.x, f23.y};
            float gg[4] = {g01.x, g01.y, g23.x, g23.y};
            float og[4] = {o01.x, o01.y, o23.x, o23.y};
            float hn[4];
#pragma unroll
            for (int ci = 0; ci < 4; ci++) {
                float iv = sigmoidf_(ig[ci]);
                float fv = sigmoidf_(fg[ci]);
                float gv = tanhf(gg[ci]);
                float ov = sigmoidf_(og[ci]);
                float cn = fv * c[ri][ci] + iv * gv;
                c[ri][ci] = cn;
                hn[ci] = ov * tanhf(cn);
            }
            *(float4*)&h_s[tr * 4 + ri][tc * 4] = make_float4(hn[0], hn[1], hn[2], hn[3]);
        }
        __syncthreads();
    }

    // ---- fused projection: out[orow][0..63] = h_s[prow] @ Wp^T + bp ----
    float* wp = &w_s[0][0];            // reuse as [128][64]
#pragma unroll
    for (int i = 0; i < 4; i++) {      // 2048 float4 chunks, 512 thr x 4
        int q = tid + i * 512;
        *(float4*)&wp[q * 4] = *(const float4*)(d_wpT + q * 4);
    }
    __syncthreads();

    const int prow = tid >> 3;         // 0..63
    const int cg   = tid & 7;          // cols cg*8..+7
    const int orow = blockIdx.x * 64 + prow;
    u64 pacc[4] = {0ull, 0ull, 0ull, 0ull};
#pragma unroll 8
    for (int k = 0; k < 128; k++) {
        u64 hv = pack2(h_s[prow][k]);
        float4 wa = *(const float4*)&wp[k * 64 + cg * 8];
        float4 wb = *(const float4*)&wp[k * 64 + cg * 8 + 4];
        pacc[0] = fma2(hv, *(const u64*)&wa.x, pacc[0]);
        pacc[1] = fma2(hv, *(const u64*)&wa.z, pacc[1]);
        pacc[2] = fma2(hv, *(const u64*)&wb.x, pacc[2]);
        pacc[3] = fma2(hv, *(const u64*)&wb.z, pacc[3]);
    }
    float4 bpa = *(const float4*)(bp + cg * 8);
    float4 bpb = *(const float4*)(bp + cg * 8 + 4);
    float2 q0 = *(float2*)&pacc[0];
    float2 q1 = *(float2*)&pacc[1];
    float2 q2 = *(float2*)&pacc[2];
    float2 q3 = *(float2*)&pacc[3];
    float4 o0 = make_float4(q0.x + bpa.x, q0.y + bpa.y, q1.x + bpa.z, q1.y + bpa.w);
    float4 o1 = make_float4(q2.x + bpb.x, q2.y + bpb.y, q3.x + bpb.z, q3.y + bpb.w);
    *(float4*)(out + (size_t)orow * 64 + cg * 8)     = o0;
    *(float4*)(out + (size_t)orow * 64 + cg * 8 + 4) = o1;
}

// ---------------- launch --------------------------------------------------------
#define GCN_SMEM64  (4 * 128 * 72 * 2 + 16 * 128 * 4)
#define GCN_SMEM128 (4 * 128 * 136 * 2 + 16 * 128 * 4)

extern "C" void kernel_launch(void* const* d_in, const int* in_sizes, int n_in,
                              void* d_out, int out_size)
{
    const float* x_seq = (const float*)d_in[0];
    const int*   ei    = (const int*)  d_in[1];
    const float* ew    = (const float*)d_in[2];
    const float* W0s   = (const float*)d_in[3];
    const float* b0s   = (const float*)d_in[4];
    const float* W0d   = (const float*)d_in[5];
    const float* b0d   = (const float*)d_in[6];
    const float* W1s   = (const float*)d_in[7];
    const float* b1s   = (const float*)d_in[8];
    const float* W1d   = (const float*)d_in[9];
    const float* b1d   = (const float*)d_in[10];
    const float* Wih   = (const float*)d_in[11];
    const float* Whh   = (const float*)d_in[12];
    const float* bih   = (const float*)d_in[13];
    const float* bhh   = (const float*)d_in[14];
    const float* Wp    = (const float*)d_in[15];
    const float* bp    = (const float*)d_in[16];
    float* out = (float*)d_out;

    float *h0, *gx, *b0v, *b1v;
    __nv_bfloat16 *afh, *afl, *abh, *abl, *h1hi, *h1lo;
    __nv_bfloat16 *w0sh, *w0sl, *w0dh, *w0dl, *w1sh, *w1sl, *w1dh, *w1dl;
    cudaGetSymbolAddress((void**)&h0,   d_h0);
    cudaGetSymbolAddress((void**)&gx,   d_gx);
    cudaGetSymbolAddress((void**)&afh,  d_aggfh);
    cudaGetSymbolAddress((void**)&afl,  d_aggfl);
    cudaGetSymbolAddress((void**)&abh,  d_aggbh);
    cudaGetSymbolAddress((void**)&abl,  d_aggbl);
    cudaGetSymbolAddress((void**)&h1hi, d_h1hi);
    cudaGetSymbolAddress((void**)&h1lo, d_h1lo);
    cudaGetSymbolAddress((void**)&w0sh, d_w0sh);
    cudaGetSymbolAddress((void**)&w0sl, d_w0sl);
    cudaGetSymbolAddress((void**)&w0dh, d_w0dh);
    cudaGetSymbolAddress((void**)&w0dl, d_w0dl);
    cudaGetSymbolAddress((void**)&w1sh, d_w1sh);
    cudaGetSymbolAddress((void**)&w1sl, d_w1sl);
    cudaGetSymbolAddress((void**)&w1dh, d_w1dh);
    cudaGetSymbolAddress((void**)&w1dl, d_w1dl);
    cudaGetSymbolAddress((void**)&b0v,  d_b0v);
    cudaGetSymbolAddress((void**)&b1v,  d_b1v);

    cudaFuncSetAttribute(gx_wmma_kernel,
                         cudaFuncAttributeMaxDynamicSharedMemorySize, GX_SMEM);
    cudaFuncSetAttribute((const void*)gcn_wmma_kernel<64, false>,
                         cudaFuncAttributeMaxDynamicSharedMemorySize, GCN_SMEM64);
    cudaFuncSetAttribute((const void*)gcn_wmma_kernel<128, true>,
                         cudaFuncAttributeMaxDynamicSharedMemorySize, GCN_SMEM128);

    const int M = Gn * NN;   // 128000

    // ---- CSR build + weight prep ----
    zero_kernel<<<(Gn * NN + 255) / 256, 256>>>();
    degcnt_kernel<<<(Gn * EE + 255) / 256, 256>>>(ei, ew);
    inv_kernel<<<(Gn * NN + 255) / 256, 256>>>();
    scan_kernel<<<dim3(Gn, 2), 1024>>>();
    scatter_kernel<<<(Gn * EE + 255) / 256, 256>>>(ei, ew);
    prep_kernel<<<256, 256>>>(Whh, Wp, Wih, bih, bhh,
                              W0s, W0d, W1s, W1d, b0s, b0d, b1s, b1d);

    const int gblocks = (Gn * NN * 2 * 32 + 255) / 256;

    // ---- GCN layer 0 (F=64 -> H=128) ----
    gather_kernel<64><<<gblocks, 256>>>(x_seq);
    gcn_wmma_kernel<64, false><<<M / 128, 256, GCN_SMEM64>>>(
        afh, afl, abh, abl, w0sh, w0sl, w0dh, w0dl, b0v, h0, nullptr, nullptr);

    // ---- GCN layer 1 (H=128 -> H=128) -> h1 bf16 hi/lo ----
    gather_kernel<128><<<gblocks, 256>>>(h0);
    gcn_wmma_kernel<128, true><<<M / 128, 256, GCN_SMEM128>>>(
        afh, afl, abh, abl, w1sh, w1sl, w1dh, w1dl, b1v, nullptr, h1hi, h1lo);

    // ---- LSTM input GEMM via WMMA bf16x3 ----
    gx_wmma_kernel<<<M / 128, 256, GX_SMEM>>>(gx);

    // ---- LSTM recurrence (FFMA2, 64 rows/block) + fused projection ----
    lstm_kernel<<<BNR / 64, 512>>>(out, bp);
}